// round 8
// baseline (speedup 1.0000x reference)
#include <cuda_runtime.h>

// Problem constants
static const int BB  = 8;
static const int NN  = 20000;
static const int DD  = 64;
static const int DD2 = 128;
static const int RR  = 24;
static const int SS  = 3;
static const int EE  = 60000;
static const int KK  = 101;
static const int HL  = 50;
static const int FDIM = 192;   // D + 2D
static const int ZB  = (NN + 255) / 256;   // zero-kernel blocks per snapshot

// packed fp32x2 helpers (SASS FFMA2 path)
#define FMA_F32X2(d, a, b, c) \
    asm("fma.rn.f32x2 %0, %1, %2, %3;" : "=l"(d) : "l"(a), "l"(b), "l"(c))
#define PACKF2(d, lo, hi) \
    asm("mov.b64 %0, {%1, %2};" : "=l"(d) : "f"(lo), "f"(hi))
#define UNPACKF2(lo, hi, v) \
    asm("mov.b64 {%0, %1}, %2;" : "=f"(lo), "=f"(hi) : "l"(v))

// ---------------- scratch (device globals; no allocations allowed) ----------
__device__ float g_init[BB * NN * DD];
__device__ float g_xA[BB * NN * DD];
__device__ float g_xB[BB * NN * DD];
__device__ int   g_cnt_poi[SS][NN];
__device__ int   g_cnt_dst[SS][NN];
__device__ int   g_rowstart[SS][NN];
__device__ int   g_rowfill[SS][NN];
__device__ int   g_total[SS];
__device__ int   g_csr_src[SS][EE];
__device__ int   g_csr_et[SS][EE];
__device__ float g_relsum[SS][2][NN * DD];
__device__ float2 g_Wdup[2 * DD2 * DD];    // (w,w) pairs for both GNN layers
__device__ float g_query[BB * DD];
__device__ float g_xseq[BB * HL * DD2];
__device__ float g_qkv[BB * HL * 3 * DD2];
__device__ float g_ao[BB * HL * DD2];
__device__ float g_flabel_unused[BB * DD2];

// ---------------- CSR build (batched over all S snapshots) -------------------
// also duplicates GNN weights into (w,w) pairs (s==0 tail blocks)
__global__ void k_zero_dup(const float* __restrict__ gnnW) {
    int s = blockIdx.y;
    if (blockIdx.x < ZB) {
        int i = blockIdx.x * blockDim.x + threadIdx.x;
        if (i < NN) { g_cnt_poi[s][i] = 0; g_cnt_dst[s][i] = 0; g_rowfill[s][i] = 0; }
        if (i == 0) g_total[s] = 0;
    } else if (s == 0) {
        int i = (blockIdx.x - ZB) * blockDim.x + threadIdx.x;
        if (i < 2 * DD2 * DD) {
            float w = gnnW[i];
            g_Wdup[i] = make_float2(w, w);
        }
    }
}

__global__ void k_count(const int* __restrict__ src, const int* __restrict__ dst) {
    int s = blockIdx.y;
    int e = blockIdx.x * blockDim.x + threadIdx.x;
    if (e < EE) {
        atomicAdd(&g_cnt_poi[s][src[s * EE + e]], 1);
        atomicAdd(&g_cnt_poi[s][dst[s * EE + e]], 1);
        atomicAdd(&g_cnt_dst[s][dst[s * EE + e]], 1);
    }
}

// warp-aggregated contiguous range assignment (order-free)
__global__ void k_offsets() {
    int s = blockIdx.y;
    int n = blockIdx.x * blockDim.x + threadIdx.x;
    int lane = threadIdx.x & 31;
    int c = (n < NN) ? g_cnt_dst[s][n] : 0;
    int pre = c;
    #pragma unroll
    for (int off = 1; off < 32; off <<= 1) {
        int t = __shfl_up_sync(0xffffffffu, pre, off);
        if (lane >= off) pre += t;
    }
    int tot = __shfl_sync(0xffffffffu, pre, 31);
    int base = 0;
    if (lane == 31 && tot > 0) base = atomicAdd(&g_total[s], tot);
    base = __shfl_sync(0xffffffffu, base, 31);
    if (n < NN) g_rowstart[s][n] = base + pre - c;
}

__global__ void k_scatter(const int* __restrict__ src, const int* __restrict__ dst,
                          const int* __restrict__ et) {
    int s = blockIdx.y;
    int e = blockIdx.x * blockDim.x + threadIdx.x;
    if (e < EE) {
        int dn = dst[s * EE + e];
        int pos = g_rowstart[s][dn] + atomicAdd(&g_rowfill[s][dn], 1);
        g_csr_src[s][pos] = src[s * EE + e];
        g_csr_et[s][pos]  = et[s * EE + e];
    }
}

// relsum for all (s, layer) + snapshot-0 init (batch-invariant)
__global__ void k_relsum_init0(const float* __restrict__ rel,
                               const float* __restrict__ poi) {
    int s = blockIdx.y;
    int i = blockIdx.x * blockDim.x + threadIdx.x;  // NN*DD
    if (i >= NN * DD) return;
    int n = i >> 6, j = i & 63;
    int rs = g_rowstart[s][n], cnt = g_cnt_dst[s][n];
    float a0 = 0.f, a1 = 0.f;
    for (int p = rs; p < rs + cnt; p++) {
        int r = __ldg(&g_csr_et[s][p]);
        a0 += __ldg(&rel[r * DD + j]);
        a1 += __ldg(&rel[RR * DD + r * DD + j]);
    }
    g_relsum[s][0][i] = a0;
    g_relsum[s][1][i] = a1;
    if (s == 0) g_init[i] = (float)g_cnt_poi[0][n] * poi[i];
}

// 16 rows per block, 256 threads. prev output in g_xB; prevBS = 0 (b0 bcast) or NN*DD.
__global__ void k_gate_init(const float* __restrict__ poi,
                            const float* __restrict__ gW,
                            const float* __restrict__ gb, int prevBS, int s) {
    const int P = 20;
    __shared__ float s_in[DD * P];
    int n0 = blockIdx.x * 16;
    int b  = blockIdx.y;
    int tid = threadIdx.x;
    int j   = tid & 63;
    int gbk = tid >> 6;
    #pragma unroll
    for (int gi = 0; gi < 4; gi++) {
        int g = gbk * 4 + gi;
        int n = n0 + g;
        s_in[j * P + g] = g_xB[b * prevBS + n * DD + j];
    }
    __syncthreads();
    float bj = gb[j];
    unsigned long long acc01, acc23;
    PACKF2(acc01, bj, bj);
    acc23 = acc01;
    #pragma unroll 8
    for (int k = 0; k < DD; k++) {
        float w = __ldg(&gW[k * DD + j]);
        unsigned long long wd;
        PACKF2(wd, w, w);
        ulonglong2 x = *reinterpret_cast<const ulonglong2*>(&s_in[k * P + gbk * 4]);
        FMA_F32X2(acc01, wd, x.x, acc01);
        FMA_F32X2(acc23, wd, x.y, acc23);
    }
    float accs[4];
    UNPACKF2(accs[0], accs[1], acc01);
    UNPACKF2(accs[2], accs[3], acc23);
    #pragma unroll
    for (int gi = 0; gi < 4; gi++) {
        int g = gbk * 4 + gi;
        int n = n0 + g;
        float gt = 1.f / (1.f + __expf(-accs[gi]));
        float prv = s_in[j * P + g];
        float ione = (float)g_cnt_poi[s][n] * poi[n * DD + j];
        g_init[(b * NN + n) * DD + j] = ione * gt + (1.f - gt) * prv;
    }
}

// ---------------- fused GNN layer: gather + [agg|init] @ W + ReLU ------------
// 512 threads: 8 j-groups gather 2 nodes each; lower 128 do GEMM (8 nodes/thread).
__global__ void k_layer(int s, int layer, const float* __restrict__ bias) {
    const int P = 20;
    __shared__ float s_in[2 * DD * P];
    int n0 = blockIdx.x * 16;
    int b  = blockIdx.y;
    int tid = threadIdx.x;
    int j   = tid & 63;
    int grp = tid >> 6;              // 0..7
    const float* xin  = (layer == 0) ? g_init : g_xA;
    float*       xout = (layer == 0) ? g_xA : g_xB;
    const float* relsum = g_relsum[s][layer];
    const int* csr = g_csr_src[s];
    const float* xb = xin + b * NN * DD;
    #pragma unroll
    for (int gi = 0; gi < 2; gi++) {
        int g = grp * 2 + gi;
        int n = n0 + g;
        int rs = g_rowstart[s][n], cnt = g_cnt_dst[s][n];
        float acc = __ldg(&relsum[n * DD + j]);
        for (int p = rs; p < rs + cnt; p++)
            acc += xb[__ldg(&csr[p]) * DD + j];
        s_in[j * P + g] = acc;
        s_in[(DD + j) * P + g] = g_init[(b * NN + n) * DD + j];
    }
    __syncthreads();
    if (tid < 128) {
        int ng = tid >> 6;           // 0..1 : nodes ng*8 .. ng*8+7
        const unsigned long long* Wd =
            reinterpret_cast<const unsigned long long*>(g_Wdup + layer * DD2 * DD);
        float bj = bias[j];
        unsigned long long a0, a1, a2, a3;
        PACKF2(a0, bj, bj);
        a1 = a0; a2 = a0; a3 = a0;
        #pragma unroll 8
        for (int k = 0; k < 2 * DD; k++) {
            unsigned long long wd = __ldg(&Wd[k * DD + j]);
            const float* base = &s_in[k * P + ng * 8];
            ulonglong2 xlo = *reinterpret_cast<const ulonglong2*>(base);
            ulonglong2 xhi = *reinterpret_cast<const ulonglong2*>(base + 4);
            FMA_F32X2(a0, wd, xlo.x, a0);
            FMA_F32X2(a1, wd, xlo.y, a1);
            FMA_F32X2(a2, wd, xhi.x, a2);
            FMA_F32X2(a3, wd, xhi.y, a3);
        }
        unsigned long long accs[4] = {a0, a1, a2, a3};
        #pragma unroll
        for (int q = 0; q < 4; q++) {
            float lo, hi;
            UNPACKF2(lo, hi, accs[q]);
            int n = n0 + ng * 8 + q * 2;
            xout[(b * NN + n) * DD + j]     = fmaxf(lo, 0.f);
            xout[(b * NN + n + 1) * DD + j] = fmaxf(hi, 0.f);
        }
    }
}

// ---------------- full query chain in one launch ------------------------------
__global__ void k_query(const float* __restrict__ qe, const int* __restrict__ ridx,
                        const float* __restrict__ temb, const int* __restrict__ gtime,
                        const float* __restrict__ lw, const float* __restrict__ lb) {
    __shared__ float sq[BB * DD];
    int tid = threadIdx.x;           // 512
    int b = tid >> 6, d = tid & 63;
    float q = qe[ridx[b] * DD + d];
    for (int s = 0; s < SS; s++) {
        sq[tid] = q + temb[gtime[s] * DD + d];
        __syncthreads();
        float acc = lb[d];
        #pragma unroll 8
        for (int k = 0; k < DD; k++) acc = fmaf(sq[b * DD + k], lw[k * DD + d], acc);
        q = acc;
        __syncthreads();
    }
    g_query[tid] = q;
}

// ---------------- sequence build + transformer -------------------------------
__global__ void k_xseq(const int* __restrict__ hp, const float* __restrict__ hte) {
    int row = blockIdx.x;            // 0..B*HL-1
    int b = row / HL;
    int j = threadIdx.x;             // 128
    int p = hp[row];
    float v = (j < DD) ? g_xB[(b * NN + p) * DD + j] : g_query[b * DD + (j - DD)];
    g_xseq[row * DD2 + j] = v + hte[row * DD2 + j];
}

__global__ void k_qkv(const float* __restrict__ Wqkv, int l) {
    __shared__ float sx[DD2];
    int row = blockIdx.x;
    int c = threadIdx.x;             // 384
    if (c < DD2) sx[c] = g_xseq[row * DD2 + c];
    __syncthreads();
    const float* W = Wqkv + l * DD2 * 3 * DD2;
    float acc = 0.f;
    #pragma unroll 8
    for (int k = 0; k < DD2; k++) acc = fmaf(sx[k], __ldg(&W[k * 384 + c]), acc);
    g_qkv[row * 384 + c] = acc;
}

__global__ void k_att() {
    const int PQ = 65;
    __shared__ float sq[HL * PQ];
    __shared__ float sk[HL * PQ];
    __shared__ float sv[HL * PQ];
    __shared__ float ss[HL * HL];
    int b = blockIdx.x, h = blockIdx.y;
    int tid = threadIdx.x;           // 256
    for (int i = tid; i < HL * DD; i += 256) {
        int t = i / DD, d = i & 63;
        int base = (b * HL + t) * 384 + h * 64 + d;
        sq[t * PQ + d] = g_qkv[base];
        sk[t * PQ + d] = g_qkv[base + 128];
        sv[t * PQ + d] = g_qkv[base + 256];
    }
    __syncthreads();
    for (int o = tid; o < HL * HL; o += 256) {
        int i = o / HL, jj = o % HL;
        float acc = 0.f;
        #pragma unroll 8
        for (int d = 0; d < 64; d++) acc = fmaf(sq[i * PQ + d], sk[jj * PQ + d], acc);
        ss[o] = acc * 0.125f;
    }
    __syncthreads();
    for (int i = tid; i < HL; i += 256) {
        float m = -1e30f;
        for (int jj = 0; jj < HL; jj++) m = fmaxf(m, ss[i * HL + jj]);
        float sum = 0.f;
        for (int jj = 0; jj < HL; jj++) { float e = __expf(ss[i * HL + jj] - m); ss[i * HL + jj] = e; sum += e; }
        float inv = 1.f / sum;
        for (int jj = 0; jj < HL; jj++) ss[i * HL + jj] *= inv;
    }
    __syncthreads();
    for (int o = tid; o < HL * DD; o += 256) {
        int i = o / DD, d = o & 63;
        float acc = 0.f;
        #pragma unroll 5
        for (int jj = 0; jj < HL; jj++) acc = fmaf(ss[i * HL + jj], sv[jj * PQ + d], acc);
        g_ao[(b * HL + i) * DD2 + h * 64 + d] = acc;
    }
}

// ---- fused proj + LN1 + FF1 + FF2 + LN2 (one block per row, 128 threads) ----
__global__ void k_ffn(const float* __restrict__ Wo, const float* __restrict__ ln1,
                      const float* __restrict__ W1, const float* __restrict__ b1,
                      const float* __restrict__ W2, const float* __restrict__ b2,
                      const float* __restrict__ ln2, int l) {
    __shared__ float so[DD2];
    __shared__ float xs[DD2];
    __shared__ float sh[512];
    __shared__ float red[DD2];
    int row = blockIdx.x;
    int j = threadIdx.x;             // 128
    so[j] = g_ao[row * DD2 + j];
    __syncthreads();
    const float* W = Wo + l * DD2 * DD2;
    float acc = 0.f;
    #pragma unroll 8
    for (int k = 0; k < DD2; k++) acc = fmaf(so[k], __ldg(&W[k * DD2 + j]), acc);
    float v = g_xseq[row * DD2 + j] + acc;
    red[j] = v;
    __syncthreads();
    for (int off = 64; off > 0; off >>= 1) { if (j < off) red[j] += red[j + off]; __syncthreads(); }
    float mean = red[0] * (1.f / 128.f);
    __syncthreads();
    float dv = v - mean;
    red[j] = dv * dv;
    __syncthreads();
    for (int off = 64; off > 0; off >>= 1) { if (j < off) red[j] += red[j + off]; __syncthreads(); }
    float var = red[0] * (1.f / 128.f);
    __syncthreads();
    const float* ln1l = ln1 + l * 2 * DD2;
    float xv = dv * rsqrtf(var + 1e-5f) * ln1l[j] + ln1l[DD2 + j];
    xs[j] = xv;
    __syncthreads();
    const float* W1l = W1 + l * DD2 * 512;
    float4 a1 = __ldg((const float4*)&b1[l * 512 + j * 4]);
    #pragma unroll 8
    for (int k = 0; k < DD2; k++) {
        float x = xs[k];
        float4 w = __ldg((const float4*)&W1l[k * 512 + j * 4]);
        a1.x = fmaf(x, w.x, a1.x); a1.y = fmaf(x, w.y, a1.y);
        a1.z = fmaf(x, w.z, a1.z); a1.w = fmaf(x, w.w, a1.w);
    }
    float4 r1;
    r1.x = fmaxf(a1.x, 0.f); r1.y = fmaxf(a1.y, 0.f);
    r1.z = fmaxf(a1.z, 0.f); r1.w = fmaxf(a1.w, 0.f);
    *(float4*)&sh[j * 4] = r1;
    __syncthreads();
    const float* W2l = W2 + l * 512 * DD2;
    float a2 = b2[l * DD2 + j];
    #pragma unroll 8
    for (int k = 0; k < 512; k++) a2 = fmaf(sh[k], __ldg(&W2l[k * DD2 + j]), a2);
    float v2 = xs[j] + a2;
    red[j] = v2;
    __syncthreads();
    for (int off = 64; off > 0; off >>= 1) { if (j < off) red[j] += red[j + off]; __syncthreads(); }
    float mean2 = red[0] * (1.f / 128.f);
    __syncthreads();
    float dv2 = v2 - mean2;
    red[j] = dv2 * dv2;
    __syncthreads();
    for (int off = 64; off > 0; off >>= 1) { if (j < off) red[j] += red[j + off]; __syncthreads(); }
    float var2 = red[0] * (1.f / 128.f);
    const float* ln2l = ln2 + l * 2 * DD2;
    g_xseq[row * DD2 + j] = dv2 * rsqrtf(var2 + 1e-5f) * ln2l[j] + ln2l[DD2 + j];
}

// ---------------- final scoring MLP (flabel computed inline) -------------------
__global__ void k_score(const int* __restrict__ tidx,
                        const float* __restrict__ W1, const float* __restrict__ b1,
                        const float* __restrict__ W2, const float* __restrict__ b2,
                        float* __restrict__ out) {
    __shared__ float ft[FDIM];
    __shared__ float sh[256];
    int blk = blockIdx.x;
    int b = blk / KK;
    int j = threadIdx.x;             // 192
    int ti = tidx[blk];
    float v;
    if (j < DD) {
        v = g_xB[(b * NN + ti) * DD + j];
    } else {
        int c = j - DD;
        float ssum = 0.f;
        #pragma unroll 10
        for (int t = 0; t < HL; t++) ssum += g_xseq[(b * HL + t) * DD2 + c];
        v = ssum * (1.f / (float)HL);
    }
    ft[j] = v;
    if (j < 64) sh[192 + j] = 0.f;
    __syncthreads();
    float acc = b1[j];
    #pragma unroll 8
    for (int q = 0; q < FDIM; q++) acc = fmaf(ft[q], __ldg(&W1[q * FDIM + j]), acc);
    float h = fmaxf(acc, 0.f);
    sh[j] = h * W2[j];
    __syncthreads();
    for (int off = 128; off > 0; off >>= 1) { if (j < off) sh[j] += sh[j + off]; __syncthreads(); }
    if (j == 0) out[blk] = sh[0] + b2[0];
}

// ---------------- host launcher -------------------------------------------------
extern "C" void kernel_launch(void* const* d_in, const int* in_sizes, int n_in,
                              void* d_out, int out_size) {
    const float* poi   = (const float*)d_in[0];
    const float* qemb  = (const float*)d_in[1];
    const float* gateW = (const float*)d_in[2];
    const float* gateb = (const float*)d_in[3];
    const float* gnn_rel = (const float*)d_in[4];
    const float* gnn_W   = (const float*)d_in[5];
    const float* gnn_b   = (const float*)d_in[6];
    const float* gte  = (const float*)d_in[7];
    const float* glW  = (const float*)d_in[8];
    const float* glb  = (const float*)d_in[9];
    const float* Wqkv = (const float*)d_in[10];
    const float* Wo   = (const float*)d_in[11];
    const float* ln1  = (const float*)d_in[12];
    const float *W1, *b1, *W2, *b2, *ln2;
    if (in_sizes[13] == 2 * 2 * DD2) {       // dict order: ln2 right after ln1
        ln2 = (const float*)d_in[13];
        W1  = (const float*)d_in[14];
        b1  = (const float*)d_in[15];
        W2  = (const float*)d_in[16];
        b2  = (const float*)d_in[17];
    } else {                                 // signature order
        W1  = (const float*)d_in[13];
        b1  = (const float*)d_in[14];
        W2  = (const float*)d_in[15];
        b2  = (const float*)d_in[16];
        ln2 = (const float*)d_in[17];
    }
    const float* mW1 = (const float*)d_in[18];
    const float* mb1 = (const float*)d_in[19];
    const float* mW2 = (const float*)d_in[20];
    const float* mb2 = (const float*)d_in[21];
    const float* hte = (const float*)d_in[22];
    const int* esrc  = (const int*)d_in[23];
    const int* edst  = (const int*)d_in[24];
    const int* etyp  = (const int*)d_in[25];
    const int* ridx  = (const int*)d_in[27];
    const int* tidx  = (const int*)d_in[28];
    const int* hpoi  = (const int*)d_in[29];
    const int* gtime = (const int*)d_in[30];
    float* out = (float*)d_out;

    // CSR + weight dup (5 launches; launch #6 overall = first k_layer for ncu)
    k_zero_dup<<<dim3(ZB + 64, SS), 256>>>(gnn_W);
    k_count<<<dim3((EE + 255) / 256, SS), 256>>>(esrc, edst);
    k_offsets<<<dim3((NN + 255) / 256, SS), 256>>>();
    k_scatter<<<dim3((EE + 255) / 256, SS), 256>>>(esrc, edst, etyp);
    k_relsum_init0<<<dim3(NN * DD / 256, SS), 256>>>(gnn_rel, poi);

    for (int s = 0; s < SS; s++) {
        int nb = (s == 0) ? 1 : BB;          // snapshot 0 is batch-invariant
        if (s > 0)
            k_gate_init<<<dim3(NN / 16, BB), 256>>>(poi, gateW, gateb,
                                                    (s == 1) ? 0 : NN * DD, s);
        for (int l = 0; l < 2; l++)
            k_layer<<<dim3(NN / 16, nb), 512>>>(s, l, gnn_b + l * DD);
    }

    k_query<<<1, BB * DD>>>(qemb, ridx, gte, gtime, glW, glb);
    k_xseq<<<BB * HL, DD2>>>(hpoi, hte);
    for (int l = 0; l < 2; l++) {
        k_qkv<<<BB * HL, 3 * DD2>>>(Wqkv, l);
        k_att<<<dim3(BB, 2), 256>>>();
        k_ffn<<<BB * HL, DD2>>>(Wo, ln1, W1, b1, W2, b2, ln2, l);
    }
    k_score<<<BB * KK, FDIM>>>(tidx, mW1, mb1, mW2, mb2, out);
}

// round 9
// speedup vs baseline: 1.1495x; 1.1495x over previous
#include <cuda_runtime.h>

// Problem constants
static const int BB  = 8;
static const int NN  = 20000;
static const int DD  = 64;
static const int DD2 = 128;
static const int RR  = 24;
static const int SS  = 3;
static const int EE  = 60000;
static const int KK  = 101;
static const int HL  = 50;
static const int FDIM = 192;   // D + 2D
static const int VB  = 8;      // batch vector width (= BB)
static const int NPB = 4;      // nodes per block in GNN kernels
static const int ECP = 96;     // staged edges per node cap (Poisson mean 3)

// packed fp32x2 helpers (SASS FFMA2 path)
#define FMA_F32X2(d, a, b, c) \
    asm("fma.rn.f32x2 %0, %1, %2, %3;" : "=l"(d) : "l"(a), "l"(b), "l"(c))
#define PACKF2(d, lo, hi) \
    asm("mov.b64 %0, {%1, %2};" : "=l"(d) : "f"(lo), "f"(hi))
#define UNPACKF2(lo, hi, v) \
    asm("mov.b64 {%0, %1}, %2;" : "=f"(lo), "=f"(hi) : "l"(v))

// ---------------- scratch (device globals; no allocations allowed) ----------
// feature arrays in batch-minor layout: X[n][col][b] -> n*512 + col*8 + b
__device__ float g_init[NN * DD * VB];
__device__ float g_xA[NN * DD * VB];
__device__ float g_xB[NN * DD * VB];
__device__ int   g_cnt_poi[SS][NN];
__device__ int   g_cnt_dst[SS][NN];
__device__ int   g_rowstart[SS][NN];
__device__ int   g_rowfill[SS][NN];
__device__ int   g_total[SS];
__device__ int   g_csr_src[SS][EE];
__device__ int   g_csr_et[SS][EE];
__device__ float g_relsum[SS][2][NN * DD];
__device__ float g_query[BB * DD];
__device__ float g_xseq[BB * HL * DD2];
__device__ float g_qkv[BB * HL * 3 * DD2];
__device__ float g_ao[BB * HL * DD2];

// ---------------- CSR build (batched over all S snapshots) -------------------
__global__ void k_zero() {
    int s = blockIdx.y;
    int i = blockIdx.x * blockDim.x + threadIdx.x;
    if (i < NN) { g_cnt_poi[s][i] = 0; g_cnt_dst[s][i] = 0; g_rowfill[s][i] = 0; }
    if (i == 0) g_total[s] = 0;
}

__global__ void k_count(const int* __restrict__ src, const int* __restrict__ dst) {
    int s = blockIdx.y;
    int e = blockIdx.x * blockDim.x + threadIdx.x;
    if (e < EE) {
        atomicAdd(&g_cnt_poi[s][src[s * EE + e]], 1);
        atomicAdd(&g_cnt_poi[s][dst[s * EE + e]], 1);
        atomicAdd(&g_cnt_dst[s][dst[s * EE + e]], 1);
    }
}

__global__ void k_offsets() {
    int s = blockIdx.y;
    int n = blockIdx.x * blockDim.x + threadIdx.x;
    int lane = threadIdx.x & 31;
    int c = (n < NN) ? g_cnt_dst[s][n] : 0;
    int pre = c;
    #pragma unroll
    for (int off = 1; off < 32; off <<= 1) {
        int t = __shfl_up_sync(0xffffffffu, pre, off);
        if (lane >= off) pre += t;
    }
    int tot = __shfl_sync(0xffffffffu, pre, 31);
    int base = 0;
    if (lane == 31 && tot > 0) base = atomicAdd(&g_total[s], tot);
    base = __shfl_sync(0xffffffffu, base, 31);
    if (n < NN) g_rowstart[s][n] = base + pre - c;
}

__global__ void k_scatter(const int* __restrict__ src, const int* __restrict__ dst,
                          const int* __restrict__ et) {
    int s = blockIdx.y;
    int e = blockIdx.x * blockDim.x + threadIdx.x;
    if (e < EE) {
        int dn = dst[s * EE + e];
        int pos = g_rowstart[s][dn] + atomicAdd(&g_rowfill[s][dn], 1);
        g_csr_src[s][pos] = src[s * EE + e];
        g_csr_et[s][pos]  = et[s * EE + e];
    }
}

// relsum for all (s, layer) + snapshot-0 init (batch-invariant -> identical lanes)
__global__ void k_relsum_init0(const float* __restrict__ rel,
                               const float* __restrict__ poi) {
    int s = blockIdx.y;
    int i = blockIdx.x * blockDim.x + threadIdx.x;  // NN*DD
    if (i >= NN * DD) return;
    int n = i >> 6, j = i & 63;
    int rs = g_rowstart[s][n], cnt = g_cnt_dst[s][n];
    float a0 = 0.f, a1 = 0.f;
    for (int p = rs; p < rs + cnt; p++) {
        int r = __ldg(&g_csr_et[s][p]);
        a0 += __ldg(&rel[r * DD + j]);
        a1 += __ldg(&rel[RR * DD + r * DD + j]);
    }
    g_relsum[s][0][i] = a0;
    g_relsum[s][1][i] = a1;
    if (s == 0) {
        float v = (float)g_cnt_poi[0][n] * poi[i];
        float4 vv = make_float4(v, v, v, v);
        *(float4*)&g_init[n * 512 + j * 8]     = vv;
        *(float4*)&g_init[n * 512 + j * 8 + 4] = vv;
    }
}

// ---------------- gate init (s>0), batch-vectorized --------------------------
// 4 nodes/block, 256 threads: thread = (g 0..3, j 0..63); 8 batch lanes vector.
__global__ void k_gate_init(const float* __restrict__ poi,
                            const float* __restrict__ gW,
                            const float* __restrict__ gb, int s) {
    __shared__ float s_prev[NPB * DD * VB];      // 8KB
    int n0 = blockIdx.x * NPB;
    int tid = threadIdx.x;
    int j = tid & 63, g = tid >> 6;
    int n = n0 + g;
    {
        float4 p0 = *(const float4*)&g_xB[n * 512 + j * 8];
        float4 p1 = *(const float4*)&g_xB[n * 512 + j * 8 + 4];
        *(float4*)&s_prev[(g * DD + j) * 8]     = p0;
        *(float4*)&s_prev[(g * DD + j) * 8 + 4] = p1;
    }
    __syncthreads();
    float bj = gb[j];
    unsigned long long c0, c1, c2, c3;
    PACKF2(c0, bj, bj); c1 = c0; c2 = c0; c3 = c0;
    #pragma unroll 8
    for (int k = 0; k < DD; k++) {
        float w = __ldg(&gW[k * DD + j]);
        unsigned long long wd;
        PACKF2(wd, w, w);
        const float* base = &s_prev[(g * DD + k) * 8];
        ulonglong2 xlo = *(const ulonglong2*)base;
        ulonglong2 xhi = *(const ulonglong2*)(base + 4);
        FMA_F32X2(c0, wd, xlo.x, c0);
        FMA_F32X2(c1, wd, xlo.y, c1);
        FMA_F32X2(c2, wd, xhi.x, c2);
        FMA_F32X2(c3, wd, xhi.y, c3);
    }
    float lg[8];
    UNPACKF2(lg[0], lg[1], c0); UNPACKF2(lg[2], lg[3], c1);
    UNPACKF2(lg[4], lg[5], c2); UNPACKF2(lg[6], lg[7], c3);
    float ione = (float)g_cnt_poi[s][n] * poi[n * DD + j];
    float outv[8];
    #pragma unroll
    for (int b = 0; b < 8; b++) {
        float gt = 1.f / (1.f + __expf(-lg[b]));
        float prv = s_prev[(g * DD + j) * 8 + b];
        outv[b] = ione * gt + (1.f - gt) * prv;
    }
    *(float4*)&g_init[n * 512 + j * 8]     = make_float4(outv[0], outv[1], outv[2], outv[3]);
    *(float4*)&g_init[n * 512 + j * 8 + 4] = make_float4(outv[4], outv[5], outv[6], outv[7]);
}

// ---------------- fused GNN layer, batch-vectorized --------------------------
// 4 nodes/block, 256 threads: thread = (g, j). All 8 batches per thread.
__global__ void k_layer(int s, int layer,
                        const float* __restrict__ W,
                        const float* __restrict__ bias) {
    __shared__ float s_in[NPB * DD2 * VB];       // 16KB : [g][k 0..127][b]
    __shared__ int   s_edge[NPB * ECP];
    int n0 = blockIdx.x * NPB;
    int tid = threadIdx.x;
    int j = tid & 63, g = tid >> 6;
    int n = n0 + g;
    const float* xin  = (layer == 0) ? g_init : g_xA;
    float*       xout = (layer == 0) ? g_xA : g_xB;
    const float* relsum = g_relsum[s][layer];
    const int* csr = g_csr_src[s];
    int rs = g_rowstart[s][n];
    int cnt = g_cnt_dst[s][n];
    // stage edge indices (threads j<cnt cooperate; cnt rarely > 64, never ~96)
    int staged = (cnt < ECP) ? cnt : ECP;
    for (int q = j; q < staged; q += 64)
        s_edge[g * ECP + q] = __ldg(&csr[rs + q]);
    // init half of the concat
    {
        float4 p0 = *(const float4*)&g_init[n * 512 + j * 8];
        float4 p1 = *(const float4*)&g_init[n * 512 + j * 8 + 4];
        *(float4*)&s_in[(g * DD2 + DD + j) * 8]     = p0;
        *(float4*)&s_in[(g * DD2 + DD + j) * 8 + 4] = p1;
    }
    __syncthreads();
    // gather: vector accumulate over edges (all 8 batches per load pair)
    float rv = __ldg(&relsum[n * DD + j]);
    float4 aA = make_float4(rv, rv, rv, rv);
    float4 aB = aA;
    for (int e = 0; e < staged; e++) {
        int src = s_edge[g * ECP + e];
        float4 f0 = *(const float4*)&xin[src * 512 + j * 8];
        float4 f1 = *(const float4*)&xin[src * 512 + j * 8 + 4];
        aA.x += f0.x; aA.y += f0.y; aA.z += f0.z; aA.w += f0.w;
        aB.x += f1.x; aB.y += f1.y; aB.z += f1.z; aB.w += f1.w;
    }
    for (int p = rs + staged; p < rs + cnt; p++) {   // overflow tail (normally empty)
        int src = __ldg(&csr[p]);
        float4 f0 = *(const float4*)&xin[src * 512 + j * 8];
        float4 f1 = *(const float4*)&xin[src * 512 + j * 8 + 4];
        aA.x += f0.x; aA.y += f0.y; aA.z += f0.z; aA.w += f0.w;
        aB.x += f1.x; aB.y += f1.y; aB.z += f1.z; aB.w += f1.w;
    }
    *(float4*)&s_in[(g * DD2 + j) * 8]     = aA;
    *(float4*)&s_in[(g * DD2 + j) * 8 + 4] = aB;
    __syncthreads();
    // GEMM: out[n][j][b] = relu(bias[j] + sum_k s_in[g][k][b] * W[k][j])
    float bj = bias[j];
    unsigned long long c0, c1, c2, c3;
    PACKF2(c0, bj, bj); c1 = c0; c2 = c0; c3 = c0;
    #pragma unroll 8
    for (int k = 0; k < DD2; k++) {
        float w = __ldg(&W[k * DD + j]);
        unsigned long long wd;
        PACKF2(wd, w, w);
        const float* base = &s_in[(g * DD2 + k) * 8];
        ulonglong2 xlo = *(const ulonglong2*)base;
        ulonglong2 xhi = *(const ulonglong2*)(base + 4);
        FMA_F32X2(c0, wd, xlo.x, c0);
        FMA_F32X2(c1, wd, xlo.y, c1);
        FMA_F32X2(c2, wd, xhi.x, c2);
        FMA_F32X2(c3, wd, xhi.y, c3);
    }
    float o[8];
    UNPACKF2(o[0], o[1], c0); UNPACKF2(o[2], o[3], c1);
    UNPACKF2(o[4], o[5], c2); UNPACKF2(o[6], o[7], c3);
    #pragma unroll
    for (int b = 0; b < 8; b++) o[b] = fmaxf(o[b], 0.f);
    *(float4*)&xout[n * 512 + j * 8]     = make_float4(o[0], o[1], o[2], o[3]);
    *(float4*)&xout[n * 512 + j * 8 + 4] = make_float4(o[4], o[5], o[6], o[7]);
}

// ---------------- full query chain in one launch ------------------------------
__global__ void k_query(const float* __restrict__ qe, const int* __restrict__ ridx,
                        const float* __restrict__ temb, const int* __restrict__ gtime,
                        const float* __restrict__ lw, const float* __restrict__ lb) {
    __shared__ float sq[BB * DD];
    int tid = threadIdx.x;           // 512
    int b = tid >> 6, d = tid & 63;
    float q = qe[ridx[b] * DD + d];
    for (int s = 0; s < SS; s++) {
        sq[tid] = q + temb[gtime[s] * DD + d];
        __syncthreads();
        float acc = lb[d];
        #pragma unroll 8
        for (int k = 0; k < DD; k++) acc = fmaf(sq[b * DD + k], lw[k * DD + d], acc);
        q = acc;
        __syncthreads();
    }
    g_query[tid] = q;
}

// ---------------- sequence build + transformer -------------------------------
__global__ void k_xseq(const int* __restrict__ hp, const float* __restrict__ hte) {
    int row = blockIdx.x;            // 0..B*HL-1
    int b = row / HL;
    int j = threadIdx.x;             // 128
    int p = hp[row];
    float v = (j < DD) ? g_xB[p * 512 + j * 8 + b] : g_query[b * DD + (j - DD)];
    g_xseq[row * DD2 + j] = v + hte[row * DD2 + j];
}

__global__ void k_qkv(const float* __restrict__ Wqkv, int l) {
    __shared__ float sx[DD2];
    int row = blockIdx.x;
    int c = threadIdx.x;             // 384
    if (c < DD2) sx[c] = g_xseq[row * DD2 + c];
    __syncthreads();
    const float* W = Wqkv + l * DD2 * 3 * DD2;
    float acc = 0.f;
    #pragma unroll 8
    for (int k = 0; k < DD2; k++) acc = fmaf(sx[k], __ldg(&W[k * 384 + c]), acc);
    g_qkv[row * 384 + c] = acc;
}

__global__ void k_att() {
    const int PQ = 65;
    __shared__ float sq[HL * PQ];
    __shared__ float sk[HL * PQ];
    __shared__ float sv[HL * PQ];
    __shared__ float ss[HL * HL];
    int b = blockIdx.x, h = blockIdx.y;
    int tid = threadIdx.x;           // 256
    for (int i = tid; i < HL * DD; i += 256) {
        int t = i / DD, d = i & 63;
        int base = (b * HL + t) * 384 + h * 64 + d;
        sq[t * PQ + d] = g_qkv[base];
        sk[t * PQ + d] = g_qkv[base + 128];
        sv[t * PQ + d] = g_qkv[base + 256];
    }
    __syncthreads();
    for (int o = tid; o < HL * HL; o += 256) {
        int i = o / HL, jj = o % HL;
        float acc = 0.f;
        #pragma unroll 8
        for (int d = 0; d < 64; d++) acc = fmaf(sq[i * PQ + d], sk[jj * PQ + d], acc);
        ss[o] = acc * 0.125f;
    }
    __syncthreads();
    for (int i = tid; i < HL; i += 256) {
        float m = -1e30f;
        for (int jj = 0; jj < HL; jj++) m = fmaxf(m, ss[i * HL + jj]);
        float sum = 0.f;
        for (int jj = 0; jj < HL; jj++) { float e = __expf(ss[i * HL + jj] - m); ss[i * HL + jj] = e; sum += e; }
        float inv = 1.f / sum;
        for (int jj = 0; jj < HL; jj++) ss[i * HL + jj] *= inv;
    }
    __syncthreads();
    for (int o = tid; o < HL * DD; o += 256) {
        int i = o / DD, d = o & 63;
        float acc = 0.f;
        #pragma unroll 5
        for (int jj = 0; jj < HL; jj++) acc = fmaf(ss[i * HL + jj], sv[jj * PQ + d], acc);
        g_ao[(b * HL + i) * DD2 + h * 64 + d] = acc;
    }
}

// ---- fused proj + LN1 + FF1 + FF2 + LN2 (one block per row, 128 threads) ----
__global__ void k_ffn(const float* __restrict__ Wo, const float* __restrict__ ln1,
                      const float* __restrict__ W1, const float* __restrict__ b1,
                      const float* __restrict__ W2, const float* __restrict__ b2,
                      const float* __restrict__ ln2, int l) {
    __shared__ float so[DD2];
    __shared__ float xs[DD2];
    __shared__ float sh[512];
    __shared__ float red[DD2];
    int row = blockIdx.x;
    int j = threadIdx.x;             // 128
    so[j] = g_ao[row * DD2 + j];
    __syncthreads();
    const float* W = Wo + l * DD2 * DD2;
    float acc = 0.f;
    #pragma unroll 8
    for (int k = 0; k < DD2; k++) acc = fmaf(so[k], __ldg(&W[k * DD2 + j]), acc);
    float v = g_xseq[row * DD2 + j] + acc;
    red[j] = v;
    __syncthreads();
    for (int off = 64; off > 0; off >>= 1) { if (j < off) red[j] += red[j + off]; __syncthreads(); }
    float mean = red[0] * (1.f / 128.f);
    __syncthreads();
    float dv = v - mean;
    red[j] = dv * dv;
    __syncthreads();
    for (int off = 64; off > 0; off >>= 1) { if (j < off) red[j] += red[j + off]; __syncthreads(); }
    float var = red[0] * (1.f / 128.f);
    __syncthreads();
    const float* ln1l = ln1 + l * 2 * DD2;
    float xv = dv * rsqrtf(var + 1e-5f) * ln1l[j] + ln1l[DD2 + j];
    xs[j] = xv;
    __syncthreads();
    const float* W1l = W1 + l * DD2 * 512;
    float4 a1 = __ldg((const float4*)&b1[l * 512 + j * 4]);
    #pragma unroll 8
    for (int k = 0; k < DD2; k++) {
        float x = xs[k];
        float4 w = __ldg((const float4*)&W1l[k * 512 + j * 4]);
        a1.x = fmaf(x, w.x, a1.x); a1.y = fmaf(x, w.y, a1.y);
        a1.z = fmaf(x, w.z, a1.z); a1.w = fmaf(x, w.w, a1.w);
    }
    float4 r1;
    r1.x = fmaxf(a1.x, 0.f); r1.y = fmaxf(a1.y, 0.f);
    r1.z = fmaxf(a1.z, 0.f); r1.w = fmaxf(a1.w, 0.f);
    *(float4*)&sh[j * 4] = r1;
    __syncthreads();
    const float* W2l = W2 + l * 512 * DD2;
    float a2 = b2[l * DD2 + j];
    #pragma unroll 8
    for (int k = 0; k < 512; k++) a2 = fmaf(sh[k], __ldg(&W2l[k * DD2 + j]), a2);
    float v2 = xs[j] + a2;
    red[j] = v2;
    __syncthreads();
    for (int off = 64; off > 0; off >>= 1) { if (j < off) red[j] += red[j + off]; __syncthreads(); }
    float mean2 = red[0] * (1.f / 128.f);
    __syncthreads();
    float dv2 = v2 - mean2;
    red[j] = dv2 * dv2;
    __syncthreads();
    for (int off = 64; off > 0; off >>= 1) { if (j < off) red[j] += red[j + off]; __syncthreads(); }
    float var2 = red[0] * (1.f / 128.f);
    const float* ln2l = ln2 + l * 2 * DD2;
    g_xseq[row * DD2 + j] = dv2 * rsqrtf(var2 + 1e-5f) * ln2l[j] + ln2l[DD2 + j];
}

// ---------------- final scoring MLP (flabel inline) ---------------------------
__global__ void k_score(const int* __restrict__ tidx,
                        const float* __restrict__ W1, const float* __restrict__ b1,
                        const float* __restrict__ W2, const float* __restrict__ b2,
                        float* __restrict__ out) {
    __shared__ float ft[FDIM];
    __shared__ float sh[256];
    int blk = blockIdx.x;
    int b = blk / KK;
    int j = threadIdx.x;             // 192
    int ti = tidx[blk];
    float v;
    if (j < DD) {
        v = g_xB[ti * 512 + j * 8 + b];
    } else {
        int c = j - DD;
        float ssum = 0.f;
        #pragma unroll 10
        for (int t = 0; t < HL; t++) ssum += g_xseq[(b * HL + t) * DD2 + c];
        v = ssum * (1.f / (float)HL);
    }
    ft[j] = v;
    if (j < 64) sh[192 + j] = 0.f;
    __syncthreads();
    float acc = b1[j];
    #pragma unroll 8
    for (int q = 0; q < FDIM; q++) acc = fmaf(ft[q], __ldg(&W1[q * FDIM + j]), acc);
    float h = fmaxf(acc, 0.f);
    sh[j] = h * W2[j];
    __syncthreads();
    for (int off = 128; off > 0; off >>= 1) { if (j < off) sh[j] += sh[j + off]; __syncthreads(); }
    if (j == 0) out[blk] = sh[0] + b2[0];
}

// ---------------- host launcher -------------------------------------------------
extern "C" void kernel_launch(void* const* d_in, const int* in_sizes, int n_in,
                              void* d_out, int out_size) {
    const float* poi   = (const float*)d_in[0];
    const float* qemb  = (const float*)d_in[1];
    const float* gateW = (const float*)d_in[2];
    const float* gateb = (const float*)d_in[3];
    const float* gnn_rel = (const float*)d_in[4];
    const float* gnn_W   = (const float*)d_in[5];
    const float* gnn_b   = (const float*)d_in[6];
    const float* gte  = (const float*)d_in[7];
    const float* glW  = (const float*)d_in[8];
    const float* glb  = (const float*)d_in[9];
    const float* Wqkv = (const float*)d_in[10];
    const float* Wo   = (const float*)d_in[11];
    const float* ln1  = (const float*)d_in[12];
    const float *W1, *b1, *W2, *b2, *ln2;
    if (in_sizes[13] == 2 * 2 * DD2) {       // dict order: ln2 right after ln1
        ln2 = (const float*)d_in[13];
        W1  = (const float*)d_in[14];
        b1  = (const float*)d_in[15];
        W2  = (const float*)d_in[16];
        b2  = (const float*)d_in[17];
    } else {                                 // signature order
        W1  = (const float*)d_in[13];
        b1  = (const float*)d_in[14];
        W2  = (const float*)d_in[15];
        b2  = (const float*)d_in[16];
        ln2 = (const float*)d_in[17];
    }
    const float* mW1 = (const float*)d_in[18];
    const float* mb1 = (const float*)d_in[19];
    const float* mW2 = (const float*)d_in[20];
    const float* mb2 = (const float*)d_in[21];
    const float* hte = (const float*)d_in[22];
    const int* esrc  = (const int*)d_in[23];
    const int* edst  = (const int*)d_in[24];
    const int* etyp  = (const int*)d_in[25];
    const int* ridx  = (const int*)d_in[27];
    const int* tidx  = (const int*)d_in[28];
    const int* hpoi  = (const int*)d_in[29];
    const int* gtime = (const int*)d_in[30];
    float* out = (float*)d_out;

    // CSR (batched over snapshots)
    k_zero<<<dim3((NN + 255) / 256, SS), 256>>>();
    k_count<<<dim3((EE + 255) / 256, SS), 256>>>(esrc, edst);
    k_offsets<<<dim3((NN + 255) / 256, SS), 256>>>();
    k_scatter<<<dim3((EE + 255) / 256, SS), 256>>>(esrc, edst, etyp);
    k_relsum_init0<<<dim3(NN * DD / 256, SS), 256>>>(gnn_rel, poi);

    for (int s = 0; s < SS; s++) {
        if (s > 0)
            k_gate_init<<<NN / NPB, 256>>>(poi, gateW, gateb, s);
        for (int l = 0; l < 2; l++)
            k_layer<<<NN / NPB, 256>>>(s, l,
                                       gnn_W + l * 2 * DD * DD,
                                       gnn_b + l * DD);
    }

    k_query<<<1, BB * DD>>>(qemb, ridx, gte, gtime, glW, glb);
    k_xseq<<<BB * HL, DD2>>>(hpoi, hte);
    for (int l = 0; l < 2; l++) {
        k_qkv<<<BB * HL, 3 * DD2>>>(Wqkv, l);
        k_att<<<dim3(BB, 2), 256>>>();
        k_ffn<<<BB * HL, DD2>>>(Wo, ln1, W1, b1, W2, b2, ln2, l);
    }
    k_score<<<BB * KK, FDIM>>>(tidx, mW1, mb1, mW2, mb2, out);
}